// round 1
// baseline (speedup 1.0000x reference)
#include <cuda_runtime.h>
#include <cuda_fp16.h>
#include <cstdint>
#include <cstdio>

#define IN_F   4096
#define OUT_F  11008
#define M_TOT  8192   // 4 * 2048

// Scratch: fp16 dequantized weights [OUT_F][IN_F] and scaled activations [M_TOT][IN_F]
__device__ __half g_W[(size_t)OUT_F * IN_F];
__device__ __half g_X[(size_t)M_TOT * IN_F];

// ---------------------------------------------------------------------------
// Kernel 1: dequantize packed int4 weights -> fp16
// qweight[o][j] is a byte (stored in int32): high nibble -> col 2j, low -> 2j+1
// group index for col c is c/128 == j/64.
// ---------------------------------------------------------------------------
__global__ void dequant_kernel(const int* __restrict__ qw,
                               const float* __restrict__ scales,
                               const float* __restrict__ zeros) {
    int idx = blockIdx.x * blockDim.x + threadIdx.x;
    if (idx >= OUT_F * (IN_F / 2)) return;
    int o = idx >> 11;        // / 2048
    int j = idx & 2047;
    int v = qw[idx];
    int g = j >> 6;           // group
    float s = scales[o * 32 + g];
    float z = zeros[o * 32 + g];
    float hi = (float)((v >> 4) & 15);
    float lo = (float)(v & 15);
    __half2 w = __floats2half2_rn((hi - z) * s, (lo - z) * s);
    *reinterpret_cast<__half2*>(g_W + (size_t)o * IN_F + 2 * j) = w;
}

// ---------------------------------------------------------------------------
// Kernel 2: xs = x * input_scale -> fp16  (vectorized by 4)
// ---------------------------------------------------------------------------
__global__ void xscale_kernel(const float* __restrict__ x,
                              const float* __restrict__ iscale) {
    int i = blockIdx.x * blockDim.x + threadIdx.x;
    if (i >= (M_TOT * IN_F) / 4) return;
    float4 xv = reinterpret_cast<const float4*>(x)[i];
    int k = (i * 4) & (IN_F - 1);
    float4 sv = *reinterpret_cast<const float4*>(iscale + k);
    __half2 h0 = __floats2half2_rn(xv.x * sv.x, xv.y * sv.y);
    __half2 h1 = __floats2half2_rn(xv.z * sv.z, xv.w * sv.w);
    reinterpret_cast<__half2*>(g_X)[2 * i]     = h0;
    reinterpret_cast<__half2*>(g_X)[2 * i + 1] = h1;
}

// ---------------------------------------------------------------------------
// Kernel 3: C[M,N] = Xs[M,K] * W[N,K]^T + bias, fp16 in / fp32 accum.
// BM=BN=128, BK=32, 256 threads (8 warps as 4x2), mma.sync m16n8k16,
// cp.async double buffering, 16B-padded smem rows (stride 80B, conflict-free
// for ldmatrix 8-row groups).
// ---------------------------------------------------------------------------
#define BM 128
#define BN 128
#define BK 32
#define ASTR 40   // BK + 8 halves pad -> 80-byte row stride

__device__ __forceinline__ uint32_t smem_u32(const void* p) {
    return (uint32_t)__cvta_generic_to_shared(p);
}

__global__ __launch_bounds__(256)
void gemm_kernel(const float* __restrict__ bias, float* __restrict__ C) {
    __shared__ __half As[2][BM * ASTR];
    __shared__ __half Bs[2][BN * ASTR];

    const int tid  = threadIdx.x;
    const int lane = tid & 31;
    const int wid  = tid >> 5;
    const int wm   = wid & 3;    // warp row (32 rows each)
    const int wn   = wid >> 2;   // warp col (64 cols each)
    const int m0   = blockIdx.y * BM;
    const int n0   = blockIdx.x * BN;

    float acc[2][8][4];
    #pragma unroll
    for (int i = 0; i < 2; i++)
        #pragma unroll
        for (int j = 0; j < 8; j++)
            #pragma unroll
            for (int k = 0; k < 4; k++) acc[i][j][k] = 0.f;

    auto issue = [&](int kt, int buf) {
        #pragma unroll
        for (int i = 0; i < 2; i++) {
            int id  = tid + i * 256;          // 512 16B-chunks per tile
            int row = id >> 2, c = id & 3;
            const __half* srcA = g_X + (size_t)(m0 + row) * IN_F + kt * BK + c * 8;
            uint32_t dstA = smem_u32(&As[buf][row * ASTR + c * 8]);
            asm volatile("cp.async.cg.shared.global [%0], [%1], 16;\n" :: "r"(dstA), "l"(srcA));
            const __half* srcB = g_W + (size_t)(n0 + row) * IN_F + kt * BK + c * 8;
            uint32_t dstB = smem_u32(&Bs[buf][row * ASTR + c * 8]);
            asm volatile("cp.async.cg.shared.global [%0], [%1], 16;\n" :: "r"(dstB), "l"(srcB));
        }
        asm volatile("cp.async.commit_group;\n");
    };

    issue(0, 0);
    asm volatile("cp.async.wait_group 0;\n");
    __syncthreads();

    const int KT = IN_F / BK;   // 128 k-tiles
    for (int kt = 0; kt < KT; kt++) {
        int buf = kt & 1;
        if (kt + 1 < KT) issue(kt + 1, buf ^ 1);

        uint32_t a_base = smem_u32(&As[buf][0]);
        uint32_t b_base = smem_u32(&Bs[buf][0]);

        #pragma unroll
        for (int kk = 0; kk < 2; kk++) {
            uint32_t a[2][4];
            #pragma unroll
            for (int mt = 0; mt < 2; mt++) {
                int row = wm * 32 + mt * 16 + (lane & 15);
                int col = kk * 16 + (lane >> 4) * 8;
                uint32_t addr = a_base + (uint32_t)(row * ASTR + col) * 2;
                asm volatile("ldmatrix.sync.aligned.m8n8.x4.shared.b16 {%0,%1,%2,%3}, [%4];"
                    : "=r"(a[mt][0]), "=r"(a[mt][1]), "=r"(a[mt][2]), "=r"(a[mt][3])
                    : "r"(addr));
            }
            uint32_t b[8][2];
            #pragma unroll
            for (int ntp = 0; ntp < 4; ntp++) {
                int mi = lane >> 3, r = lane & 7;
                int n = wn * 64 + ntp * 16 + (mi >> 1) * 8 + r;
                int k = kk * 16 + (mi & 1) * 8;
                uint32_t addr = b_base + (uint32_t)(n * ASTR + k) * 2;
                uint32_t r0, r1, r2, r3;
                asm volatile("ldmatrix.sync.aligned.m8n8.x4.shared.b16 {%0,%1,%2,%3}, [%4];"
                    : "=r"(r0), "=r"(r1), "=r"(r2), "=r"(r3) : "r"(addr));
                b[2 * ntp][0]     = r0; b[2 * ntp][1]     = r1;
                b[2 * ntp + 1][0] = r2; b[2 * ntp + 1][1] = r3;
            }
            #pragma unroll
            for (int mt = 0; mt < 2; mt++)
                #pragma unroll
                for (int nt = 0; nt < 8; nt++) {
                    asm volatile(
                        "mma.sync.aligned.m16n8k16.row.col.f32.f16.f16.f32 "
                        "{%0,%1,%2,%3}, {%4,%5,%6,%7}, {%8,%9}, {%0,%1,%2,%3};"
                        : "+f"(acc[mt][nt][0]), "+f"(acc[mt][nt][1]),
                          "+f"(acc[mt][nt][2]), "+f"(acc[mt][nt][3])
                        : "r"(a[mt][0]), "r"(a[mt][1]), "r"(a[mt][2]), "r"(a[mt][3]),
                          "r"(b[nt][0]), "r"(b[nt][1]));
                }
        }
        asm volatile("cp.async.wait_group 0;\n");
        __syncthreads();
    }

    // Epilogue: acc + bias -> C (fp32), float2 stores
    #pragma unroll
    for (int mt = 0; mt < 2; mt++) {
        int row = m0 + wm * 32 + mt * 16 + (lane >> 2);
        #pragma unroll
        for (int nt = 0; nt < 8; nt++) {
            int col = n0 + wn * 64 + nt * 8 + (lane & 3) * 2;
            float2 bv = *reinterpret_cast<const float2*>(bias + col);
            float2 v0 = make_float2(acc[mt][nt][0] + bv.x, acc[mt][nt][1] + bv.y);
            float2 v1 = make_float2(acc[mt][nt][2] + bv.x, acc[mt][nt][3] + bv.y);
            *reinterpret_cast<float2*>(C + (size_t)row * OUT_F + col)       = v0;
            *reinterpret_cast<float2*>(C + (size_t)(row + 8) * OUT_F + col) = v1;
        }
    }
}

// ---------------------------------------------------------------------------
// Launch
// ---------------------------------------------------------------------------
extern "C" void kernel_launch(void* const* d_in, const int* in_sizes, int n_in,
                              void* d_out, int out_size) {
    const float* x      = (const float*)d_in[0];
    const int*   qw     = (const int*)  d_in[1];
    const float* scales = (const float*)d_in[2];
    const float* zeros  = (const float*)d_in[3];
    const float* iscale = (const float*)d_in[4];
    const float* bias   = (const float*)d_in[5];
    float* out = (float*)d_out;

    int nq = OUT_F * (IN_F / 2);
    dequant_kernel<<<(nq + 255) / 256, 256>>>(qw, scales, zeros);

    int nx = (M_TOT * IN_F) / 4;
    xscale_kernel<<<(nx + 255) / 256, 256>>>(x, iscale);

    dim3 grid(OUT_F / BN, M_TOT / BM);   // 86 x 64 = 5504 CTAs
    gemm_kernel<<<grid, 256>>>(bias, out);
}